// round 1
// baseline (speedup 1.0000x reference)
#include <cuda_runtime.h>
#include <math.h>

#define B_    64
#define S_    512
#define EMB_  512
#define HID_  1024
#define NCTA  128
#define NC    8          // output columns per CTA
#define TPB   128
#define KC    64         // k-chunk staged per iteration
#define NCHUNK (HID_ / KC)   // 16
#define SMEM_BYTES (131072 + 32768 + 32768)  // weights + 2x dbl-buffered h chunks

// -------- scratch (static device globals; no allocation) --------
__device__ float g_pre1[(size_t)S_ * HID_ * B_];   // [t][n][b]  128 MB
__device__ float g_H1[2][HID_ * B_];               // [parity][k][m]
__device__ float g_H2[2][HID_ * B_];
__device__ unsigned g_cnt;
__device__ volatile unsigned g_gen;

// -------- grid barrier (all 128 CTAs co-resident: grid <= SM count, 1 CTA/SM by smem) ----
__device__ __forceinline__ void grid_barrier() {
    __syncthreads();
    if (threadIdx.x == 0) {
        __threadfence();                       // release prior STGs
        unsigned my = g_gen;
        if (atomicAdd(&g_cnt, 1u) == NCTA - 1) {
            atomicExch(&g_cnt, 0u);
            __threadfence();
            g_gen = my + 1;
        } else {
            while (g_gen == my) { }
        }
        __threadfence();                       // acquire
    }
    __syncthreads();
}

__device__ __forceinline__ void cp16(unsigned daddr, const void* src) {
    asm volatile("cp.async.cg.shared.global [%0], [%1], 16;" :: "r"(daddr), "l"(src));
}

// ================= precompute: pre1[t][n][b] = emb[x[b][t]] @ Wi1 + b1 =================
// grid (16, 512): blockIdx.y = t, blockIdx.x = 64-col n block. 256 threads.
__global__ __launch_bounds__(256) void pre_kernel(
    const int* __restrict__ x, const float* __restrict__ emb,
    const float* __restrict__ Wi1, const float* __restrict__ b1)
{
    __shared__ int   tok[64];
    __shared__ float As[32 * 68];   // [k][b] transposed, padded
    __shared__ float Bs[32 * 64];   // [k][n]
    const int tid = threadIdx.x;
    const int t   = blockIdx.y;
    const int n0  = blockIdx.x * 64;

    if (tid < 64) tok[tid] = x[tid * S_ + t];
    __syncthreads();

    const int ty = tid >> 4, tx = tid & 15;     // ty: b-quad, tx: n-quad
    float4 acc0 = {0,0,0,0}, acc1 = {0,0,0,0}, acc2 = {0,0,0,0}, acc3 = {0,0,0,0};

    const int b_l = tid >> 2, kq = tid & 3;
    for (int kt = 0; kt < 16; ++kt) {
        __syncthreads();
        // A tile (gathered from emb), stored transposed [k][b]
        #pragma unroll
        for (int j = 0; j < 2; ++j) {
            int k4 = kq * 4 + j * 16;
            float4 v = *(const float4*)&emb[(size_t)tok[b_l] * EMB_ + kt * 32 + k4];
            As[(k4+0)*68 + b_l] = v.x;
            As[(k4+1)*68 + b_l] = v.y;
            As[(k4+2)*68 + b_l] = v.z;
            As[(k4+3)*68 + b_l] = v.w;
        }
        // B tile
        #pragma unroll
        for (int j = 0; j < 2; ++j) {
            int kl = (tid >> 4) + j * 16;
            int nq = tid & 15;
            *(float4*)&Bs[kl*64 + nq*4] =
                *(const float4*)&Wi1[(size_t)(kt*32 + kl) * HID_ + n0 + nq*4];
        }
        __syncthreads();
        #pragma unroll
        for (int k = 0; k < 32; ++k) {
            float4 av = *(const float4*)&As[k*68 + ty*4];
            float4 bv = *(const float4*)&Bs[k*64 + tx*4];
            acc0.x += av.x*bv.x; acc0.y += av.x*bv.y; acc0.z += av.x*bv.z; acc0.w += av.x*bv.w;
            acc1.x += av.y*bv.x; acc1.y += av.y*bv.y; acc1.z += av.y*bv.z; acc1.w += av.y*bv.w;
            acc2.x += av.z*bv.x; acc2.y += av.z*bv.y; acc2.z += av.z*bv.z; acc2.w += av.z*bv.w;
            acc3.x += av.w*bv.x; acc3.y += av.w*bv.y; acc3.z += av.w*bv.z; acc3.w += av.w*bv.w;
        }
    }
    float4 b1v = *(const float4*)&b1[n0 + tx*4];
    acc0.x += b1v.x; acc0.y += b1v.y; acc0.z += b1v.z; acc0.w += b1v.w;
    acc1.x += b1v.x; acc1.y += b1v.y; acc1.z += b1v.z; acc1.w += b1v.w;
    acc2.x += b1v.x; acc2.y += b1v.y; acc2.z += b1v.z; acc2.w += b1v.w;
    acc3.x += b1v.x; acc3.y += b1v.y; acc3.z += b1v.z; acc3.w += b1v.w;

    float* outp = &g_pre1[(size_t)t * (HID_*B_)];
    float4 c;
    c = make_float4(acc0.x, acc1.x, acc2.x, acc3.x);
    *(float4*)&outp[(n0+tx*4+0)*B_ + ty*4] = c;
    c = make_float4(acc0.y, acc1.y, acc2.y, acc3.y);
    *(float4*)&outp[(n0+tx*4+1)*B_ + ty*4] = c;
    c = make_float4(acc0.z, acc1.z, acc2.z, acc3.z);
    *(float4*)&outp[(n0+tx*4+2)*B_ + ty*4] = c;
    c = make_float4(acc0.w, acc1.w, acc2.w, acc3.w);
    *(float4*)&outp[(n0+tx*4+3)*B_ + ty*4] = c;
}

// ================= persistent recurrent kernel =================
// Phase p (0..512): h1(p+1) = tanh(pre1[p] + h1(p)@Wh1)     [p<512]
//                   h2(p)   = tanh(h1(p)@Wi2 + b2 + h2(p-1)@Wh2)  [p>0]
// One grid barrier per phase. h stored [k][m] k-major for coalesced staging.
__global__ void __launch_bounds__(TPB, 1) recur_kernel(
    const float* __restrict__ Wh1, const float* __restrict__ Wi2,
    const float* __restrict__ Wh2, const float* __restrict__ b2,
    const float* __restrict__ Wd,  const float* __restrict__ bd,
    float* __restrict__ out)
{
    extern __shared__ float sm[];
    float* Ws  = sm;                 // 1024*8 float4 slots {wh1, wi2, wh2, 0}: 128 KB
    float* h1c = sm + 32768;         // 2 x [KC][64] = 32 KB
    float* h2c = sm + 40960;         // 2 x [KC][64] = 32 KB

    const int tid = threadIdx.x;
    const int c   = blockIdx.x;
    const int g   = tid >> 4;        // column within CTA slice (0..7)
    const int q   = tid & 15;        // m-quad (0..15)
    const int m4  = q << 2;
    const int col = c * NC + g;

    // weight slices -> smem, interleaved per (k, col)
    for (int idx = tid; idx < HID_ * NC; idx += TPB) {
        int k = idx >> 3, gg = idx & 7;
        int cl = c * NC + gg;
        float4 v;
        v.x = Wh1[(size_t)k * HID_ + cl];
        v.y = Wi2[(size_t)k * HID_ + cl];
        v.z = Wh2[(size_t)k * HID_ + cl];
        v.w = 0.f;
        *(float4*)&Ws[idx * 4] = v;
    }
    // zero h1(0), h2(0) (parity-0 buffers), our 512-float slice each
    {
        float4 z = {0,0,0,0};
        *(float4*)&g_H1[0][c * NC * B_ + tid * 4] = z;
        *(float4*)&g_H2[0][c * NC * B_ + tid * 4] = z;
    }
    const float b2r = b2[col];
    grid_barrier();

    const unsigned h1s = (unsigned)__cvta_generic_to_shared(h1c);
    const unsigned h2s = (unsigned)__cvta_generic_to_shared(h2c);
    const float4* ws4 = (const float4*)Ws;

    for (int p = 0; p < S_ + 1; ++p) {
        const int pr = p & 1;
        const float* H1r = g_H1[pr];       // h1(p)
        const float* H2r = g_H2[pr ^ 1];   // h2(p-1)
        const bool do1 = (p < S_), do2 = (p > 0);

        float4 a1 = {0,0,0,0};
        if (do1) a1 = *(const float4*)&g_pre1[(size_t)p * (HID_*B_) + col * B_ + m4];
        float4 a2 = {b2r, b2r, b2r, b2r};

        // prologue: stage chunk 0 into buf 0 (cp.async.cg -> bypasses L1, reads fresh L2)
        #pragma unroll
        for (int i = 0; i < 8; ++i) {
            int off = (i * TPB + tid) * 4;
            cp16(h1s + off * 4, H1r + off);
            cp16(h2s + off * 4, H2r + off);
        }
        asm volatile("cp.async.commit_group;");

        for (int ch = 0; ch < NCHUNK; ++ch) {
            if (ch + 1 < NCHUNK) {
                const int buf = (ch + 1) & 1;
                const float* s1 = H1r + (ch + 1) * (KC * B_);
                const float* s2 = H2r + (ch + 1) * (KC * B_);
                const unsigned d1 = h1s + buf * (KC * B_ * 4);
                const unsigned d2 = h2s + buf * (KC * B_ * 4);
                #pragma unroll
                for (int i = 0; i < 8; ++i) {
                    int off = (i * TPB + tid) * 4;
                    cp16(d1 + off * 4, s1 + off);
                    cp16(d2 + off * 4, s2 + off);
                }
                asm volatile("cp.async.commit_group;");
                asm volatile("cp.async.wait_group 1;");
            } else {
                asm volatile("cp.async.wait_group 0;");
            }
            __syncthreads();

            const float* h1b = h1c + (ch & 1) * (KC * B_);
            const float* h2b = h2c + (ch & 1) * (KC * B_);
            const float4* wp = ws4 + ch * (KC * NC) + g;
            #pragma unroll 8
            for (int kl = 0; kl < KC; ++kl) {
                float4 h1v = *(const float4*)&h1b[kl * B_ + m4];
                float4 h2v = *(const float4*)&h2b[kl * B_ + m4];
                float4 wv  = wp[kl * NC];
                a1.x += h1v.x * wv.x; a1.y += h1v.y * wv.x;
                a1.z += h1v.z * wv.x; a1.w += h1v.w * wv.x;
                a2.x += h1v.x * wv.y; a2.y += h1v.y * wv.y;
                a2.z += h1v.z * wv.y; a2.w += h1v.w * wv.y;
                a2.x += h2v.x * wv.z; a2.y += h2v.y * wv.z;
                a2.z += h2v.z * wv.z; a2.w += h2v.w * wv.z;
            }
            __syncthreads();
        }

        if (do1) {
            float4 o = {tanhf(a1.x), tanhf(a1.y), tanhf(a1.z), tanhf(a1.w)};
            *(float4*)&g_H1[pr ^ 1][col * B_ + m4] = o;   // h1(p+1)
        }
        if (do2) {
            float4 o = {tanhf(a2.x), tanhf(a2.y), tanhf(a2.z), tanhf(a2.w)};
            *(float4*)&g_H2[pr][col * B_ + m4] = o;       // h2(p)
        }
        grid_barrier();
    }

    // epilogue: out[b] = sigmoid(h2(512) @ Wd + bd), h2(512) lives in parity 0
    if (c == 0) {
        const int b = tid >> 1, h = tid & 1;
        const float* H2f = g_H2[0];
        float s = 0.f;
        #pragma unroll 8
        for (int k = h * 512; k < h * 512 + 512; ++k)
            s += __ldcg(&H2f[k * B_ + b]) * Wd[k];
        s += __shfl_xor_sync(0xffffffffu, s, 1);
        if (h == 0) out[b] = 1.f / (1.f + expf(-(s + bd[0])));
    }
}

// ================= launch =================
extern "C" void kernel_launch(void* const* d_in, const int* in_sizes, int n_in,
                              void* d_out, int out_size) {
    const int*   x   = (const int*)  d_in[0];
    const float* emb = (const float*)d_in[1];
    const float* Wi1 = (const float*)d_in[2];
    const float* Wh1 = (const float*)d_in[3];
    const float* b1  = (const float*)d_in[4];
    const float* Wi2 = (const float*)d_in[5];
    const float* Wh2 = (const float*)d_in[6];
    const float* b2  = (const float*)d_in[7];
    const float* Wd  = (const float*)d_in[8];
    const float* bd  = (const float*)d_in[9];
    float* out = (float*)d_out;

    cudaFuncSetAttribute(recur_kernel,
                         cudaFuncAttributeMaxDynamicSharedMemorySize, SMEM_BYTES);

    pre_kernel<<<dim3(16, 512), 256>>>(x, emb, Wi1, b1);
    recur_kernel<<<NCTA, TPB, SMEM_BYTES>>>(Wh1, Wi2, Wh2, b2, Wd, bd, out);
}

// round 3
// speedup vs baseline: 1.0066x; 1.0066x over previous
#include <cuda_runtime.h>
#include <math.h>

#define B_    64
#define S_    512
#define EMB_  512
#define HID_  1024
#define NCTA  128
#define NC    8          // output columns per CTA
#define TPB   256        // 8 warps: warp w = k-group w
#define KC    32         // k rows staged per chunk
#define NCH   (HID_ / KC)   // 32 chunks per phase

// SMEM floats: 3 duplicated weight arrays (3*16384) + h staging (8192) = 57344 floats
#define W_FLOATS   16384
#define HSTAGE_OFF 49152
#define SMEM_BYTES (57344 * 4)   // 229376 B <= 227 KB opt-in

// -------- scratch (static device globals; no allocation) --------
__device__ float g_pre1[(size_t)S_ * HID_ * B_];   // [t][n][b]
__device__ float g_H1[2][HID_ * B_];               // [parity][k][m]
__device__ float g_H2[2][HID_ * B_];
__device__ unsigned g_cnt;
__device__ volatile unsigned g_gen;

// -------- grid barrier (128 CTAs co-resident: 1 CTA/SM by smem) --------
__device__ __forceinline__ void grid_barrier() {
    __syncthreads();
    if (threadIdx.x == 0) {
        __threadfence();
        unsigned my = g_gen;
        if (atomicAdd(&g_cnt, 1u) == NCTA - 1) {
            atomicExch(&g_cnt, 0u);
            __threadfence();
            g_gen = my + 1;
        } else {
            while (g_gen == my) { }
        }
        __threadfence();
    }
    __syncthreads();
}

__device__ __forceinline__ void cp16(unsigned daddr, const void* src) {
    asm volatile("cp.async.cg.shared.global [%0], [%1], 16;" :: "r"(daddr), "l"(src));
}

// packed fp32x2 FMA: a.{lo,hi} += x.{lo,hi} * w.{lo,hi}
__device__ __forceinline__ void ffma2(unsigned long long& a,
                                      unsigned long long x,
                                      unsigned long long w) {
    asm("fma.rn.f32x2 %0, %1, %2, %0;" : "+l"(a) : "l"(x), "l"(w));
}

// ================= precompute: pre1[t][n][b] = emb[x[b][t]] @ Wi1 + b1 =================
__global__ __launch_bounds__(256) void pre_kernel(
    const int* __restrict__ x, const float* __restrict__ emb,
    const float* __restrict__ Wi1, const float* __restrict__ b1)
{
    __shared__ int   tok[64];
    __shared__ float As[32 * 68];
    __shared__ float Bs[32 * 64];
    const int tid = threadIdx.x;
    const int t   = blockIdx.y;
    const int n0  = blockIdx.x * 64;

    if (tid < 64) tok[tid] = x[tid * S_ + t];
    __syncthreads();

    const int ty = tid >> 4, tx = tid & 15;
    float4 acc0 = {0,0,0,0}, acc1 = {0,0,0,0}, acc2 = {0,0,0,0}, acc3 = {0,0,0,0};

    const int b_l = tid >> 2, kq = tid & 3;
    for (int kt = 0; kt < 16; ++kt) {
        __syncthreads();
        #pragma unroll
        for (int j = 0; j < 2; ++j) {
            int k4 = kq * 4 + j * 16;
            float4 v = *(const float4*)&emb[(size_t)tok[b_l] * EMB_ + kt * 32 + k4];
            As[(k4+0)*68 + b_l] = v.x;
            As[(k4+1)*68 + b_l] = v.y;
            As[(k4+2)*68 + b_l] = v.z;
            As[(k4+3)*68 + b_l] = v.w;
        }
        #pragma unroll
        for (int j = 0; j < 2; ++j) {
            int kl = (tid >> 4) + j * 16;
            int nq = tid & 15;
            *(float4*)&Bs[kl*64 + nq*4] =
                *(const float4*)&Wi1[(size_t)(kt*32 + kl) * HID_ + n0 + nq*4];
        }
        __syncthreads();
        #pragma unroll
        for (int k = 0; k < 32; ++k) {
            float4 av = *(const float4*)&As[k*68 + ty*4];
            float4 bv = *(const float4*)&Bs[k*64 + tx*4];
            acc0.x += av.x*bv.x; acc0.y += av.x*bv.y; acc0.z += av.x*bv.z; acc0.w += av.x*bv.w;
            acc1.x += av.y*bv.x; acc1.y += av.y*bv.y; acc1.z += av.y*bv.z; acc1.w += av.y*bv.w;
            acc2.x += av.z*bv.x; acc2.y += av.z*bv.y; acc2.z += av.z*bv.z; acc2.w += av.z*bv.w;
            acc3.x += av.w*bv.x; acc3.y += av.w*bv.y; acc3.z += av.w*bv.z; acc3.w += av.w*bv.w;
        }
    }
    float4 b1v = *(const float4*)&b1[n0 + tx*4];
    acc0.x += b1v.x; acc0.y += b1v.y; acc0.z += b1v.z; acc0.w += b1v.w;
    acc1.x += b1v.x; acc1.y += b1v.y; acc1.z += b1v.z; acc1.w += b1v.w;
    acc2.x += b1v.x; acc2.y += b1v.y; acc2.z += b1v.z; acc2.w += b1v.w;
    acc3.x += b1v.x; acc3.y += b1v.y; acc3.z += b1v.z; acc3.w += b1v.w;

    float* outp = &g_pre1[(size_t)t * (HID_*B_)];
    float4 c;
    c = make_float4(acc0.x, acc1.x, acc2.x, acc3.x);
    *(float4*)&outp[(n0+tx*4+0)*B_ + ty*4] = c;
    c = make_float4(acc0.y, acc1.y, acc2.y, acc3.y);
    *(float4*)&outp[(n0+tx*4+1)*B_ + ty*4] = c;
    c = make_float4(acc0.z, acc1.z, acc2.z, acc3.z);
    *(float4*)&outp[(n0+tx*4+2)*B_ + ty*4] = c;
    c = make_float4(acc0.w, acc1.w, acc2.w, acc3.w);
    *(float4*)&outp[(n0+tx*4+3)*B_ + ty*4] = c;
}

// ================= persistent recurrent kernel =================
// Thread (kg=warp, cp, q): cols {c0, c0+1}, batch rows m8..m8+7, k-slice of warp kg.
// Phase: all warps accumulate partials over their k slices (f32x2), reduce via smem,
// kg0 finalizes h1 (tanh+store), kg1 finalizes h2. One grid barrier per phase.
__global__ void __launch_bounds__(TPB, 1) recur_kernel(
    const float* __restrict__ Wh1, const float* __restrict__ Wi2,
    const float* __restrict__ Wh2, const float* __restrict__ b2,
    const float* __restrict__ Wd,  const float* __restrict__ bd,
    float* __restrict__ out)
{
    extern __shared__ float sm[];
    float* Wh1d = sm;                    // [k][cp] float4 {wc0,wc0,wc1,wc1}
    float* Wi2d = sm + W_FLOATS;
    float* Wh2d = sm + 2 * W_FLOATS;
    float* hst  = sm + HSTAGE_OFF;       // [buf2][h1/h2][KC][64] = 8192 floats

    const int tid  = threadIdx.x;
    const int c    = blockIdx.x;
    const int kg   = tid >> 5;           // warp = k-group 0..7
    const int lane = tid & 31;
    const int cp   = lane >> 3;          // col-pair 0..3
    const int q    = lane & 7;
    const int m8   = q * 8;
    const int c0   = c * NC + cp * 2;

    // fill duplicated weight slices
    for (int e = tid; e < HID_ * 4; e += TPB) {
        int k = e >> 2, p4 = e & 3;
        int col0 = c * NC + p4 * 2;
        float4 v;
        v.x = v.y = Wh1[(size_t)k * HID_ + col0];
        v.z = v.w = Wh1[(size_t)k * HID_ + col0 + 1];
        *(float4*)&Wh1d[e * 4] = v;
        v.x = v.y = Wi2[(size_t)k * HID_ + col0];
        v.z = v.w = Wi2[(size_t)k * HID_ + col0 + 1];
        *(float4*)&Wi2d[e * 4] = v;
        v.x = v.y = Wh2[(size_t)k * HID_ + col0];
        v.z = v.w = Wh2[(size_t)k * HID_ + col0 + 1];
        *(float4*)&Wh2d[e * 4] = v;
    }
    if (tid < 128) {
        float4 z = {0,0,0,0};
        *(float4*)&g_H1[0][c * NC * B_ + tid * 4] = z;
        *(float4*)&g_H2[0][c * NC * B_ + tid * 4] = z;
    }
    const float b2c0 = b2[c0], b2c1 = b2[c0 + 1];
    grid_barrier();

    const unsigned hs = (unsigned)__cvta_generic_to_shared(hst);

    for (int p = 0; p <= S_; ++p) {
        const int pr = p & 1;
        const float* H1r = g_H1[pr];       // h1(p)
        const float* H2r = g_H2[pr ^ 1];   // h2(p-1)

        unsigned long long a1[2][4], a2[2][4];
        #pragma unroll
        for (int cc = 0; cc < 2; ++cc)
            #pragma unroll
            for (int j = 0; j < 4; ++j) { a1[cc][j] = 0ull; a2[cc][j] = 0ull; }

        if (kg == 0 && p < S_) {
            const float* pp = &g_pre1[(size_t)p * (HID_ * B_)];
            #pragma unroll
            for (int cc = 0; cc < 2; ++cc) {
                ulonglong2 v0 = *(const ulonglong2*)&pp[(c0 + cc) * B_ + m8];
                ulonglong2 v1 = *(const ulonglong2*)&pp[(c0 + cc) * B_ + m8 + 4];
                a1[cc][0] = v0.x; a1[cc][1] = v0.y;
                a1[cc][2] = v1.x; a1[cc][3] = v1.y;
            }
        }

        // prologue: stage chunk 0 into buf 0
        #pragma unroll
        for (int j = 0; j < 2; ++j) {
            int f4 = tid + j * TPB;                 // 0..511
            cp16(hs + f4 * 16,              H1r + f4 * 4);
            cp16(hs + 2048 * 4 + f4 * 16,   H2r + f4 * 4);
        }
        asm volatile("cp.async.commit_group;");

        for (int ch = 0; ch < NCH; ++ch) {
            asm volatile("cp.async.wait_group 0;");
            __syncthreads();      // chunk ch visible; prior compute closed
            if (ch + 1 < NCH) {
                int buf = (ch + 1) & 1;
                const float* s1 = H1r + (ch + 1) * KC * B_;
                const float* s2 = H2r + (ch + 1) * KC * B_;
                #pragma unroll
                for (int j = 0; j < 2; ++j) {
                    int f4 = tid + j * TPB;
                    cp16(hs + (buf * 4096)        * 4 + f4 * 16, s1 + f4 * 4);
                    cp16(hs + (buf * 4096 + 2048) * 4 + f4 * 16, s2 + f4 * 4);
                }
                asm volatile("cp.async.commit_group;");
            }
            const int buf = ch & 1;
            const float* h1b = hst + buf * 4096;
            const float* h2b = hst + buf * 4096 + 2048;
            const int kb = ch * KC + kg * 4;        // global k of first row this warp

            #pragma unroll
            for (int kl = 0; kl < 4; ++kl) {
                const int krow = kg * 4 + kl;
                ulonglong2 h1lo = *(const ulonglong2*)&h1b[krow * 64 + m8];
                ulonglong2 h1hi = *(const ulonglong2*)&h1b[krow * 64 + m8 + 4];
                ulonglong2 h2lo = *(const ulonglong2*)&h2b[krow * 64 + m8];
                ulonglong2 h2hi = *(const ulonglong2*)&h2b[krow * 64 + m8 + 4];
                const int we = (kb + kl) * 4 + cp;
                ulonglong2 w1 = *(const ulonglong2*)&Wh1d[we * 4];
                ulonglong2 wi = *(const ulonglong2*)&Wi2d[we * 4];
                ulonglong2 w2 = *(const ulonglong2*)&Wh2d[we * 4];
                #pragma unroll
                for (int cc = 0; cc < 2; ++cc) {
                    unsigned long long w1c = cc ? w1.y : w1.x;
                    unsigned long long wic = cc ? wi.y : wi.x;
                    unsigned long long w2c = cc ? w2.y : w2.x;
                    ffma2(a1[cc][0], h1lo.x, w1c);
                    ffma2(a1[cc][1], h1lo.y, w1c);
                    ffma2(a1[cc][2], h1hi.x, w1c);
                    ffma2(a1[cc][3], h1hi.y, w1c);
                    ffma2(a2[cc][0], h1lo.x, wic);
                    ffma2(a2[cc][1], h1lo.y, wic);
                    ffma2(a2[cc][2], h1hi.x, wic);
                    ffma2(a2[cc][3], h1hi.y, wic);
                    ffma2(a2[cc][0], h2lo.x, w2c);
                    ffma2(a2[cc][1], h2lo.y, w2c);
                    ffma2(a2[cc][2], h2hi.x, w2c);
                    ffma2(a2[cc][3], h2hi.y, w2c);
                }
            }
        }
        __syncthreads();    // all chunk reads done -> reuse hst as scratch

        // write partials: A1 region floats [0,4096), A2 region [4096,8192)
        {
            int off = (kg * 32 + lane) * 16;
            ulonglong2 u;
            u.x = a1[0][0]; u.y = a1[0][1]; *(ulonglong2*)&hst[off]      = u;
            u.x = a1[0][2]; u.y = a1[0][3]; *(ulonglong2*)&hst[off + 4]  = u;
            u.x = a1[1][0]; u.y = a1[1][1]; *(ulonglong2*)&hst[off + 8]  = u;
            u.x = a1[1][2]; u.y = a1[1][3]; *(ulonglong2*)&hst[off + 12] = u;
            u.x = a2[0][0]; u.y = a2[0][1]; *(ulonglong2*)&hst[4096 + off]      = u;
            u.x = a2[0][2]; u.y = a2[0][3]; *(ulonglong2*)&hst[4096 + off + 4]  = u;
            u.x = a2[1][0]; u.y = a2[1][1]; *(ulonglong2*)&hst[4096 + off + 8]  = u;
            u.x = a2[1][2]; u.y = a2[1][3]; *(ulonglong2*)&hst[4096 + off + 12] = u;
        }
        __syncthreads();

        if (kg == 0 && p < S_) {           // finalize h1(p+1)
            float4 f[4] = {{0,0,0,0},{0,0,0,0},{0,0,0,0},{0,0,0,0}};
            #pragma unroll
            for (int g = 0; g < 8; ++g) {
                int off = (g * 32 + lane) * 16;
                #pragma unroll
                for (int j = 0; j < 4; ++j) {
                    float4 v = *(const float4*)&hst[off + j * 4];
                    f[j].x += v.x; f[j].y += v.y; f[j].z += v.z; f[j].w += v.w;
                }
            }
            float* dst = g_H1[pr ^ 1];
            float4 o;
            o = make_float4(tanhf(f[0].x), tanhf(f[0].y), tanhf(f[0].z), tanhf(f[0].w));
            *(float4*)&dst[c0 * B_ + m8] = o;
            o = make_float4(tanhf(f[1].x), tanhf(f[1].y), tanhf(f[1].z), tanhf(f[1].w));
            *(float4*)&dst[c0 * B_ + m8 + 4] = o;
            o = make_float4(tanhf(f[2].x), tanhf(f[2].y), tanhf(f[2].z), tanhf(f[2].w));
            *(float4*)&dst[(c0 + 1) * B_ + m8] = o;
            o = make_float4(tanhf(f[3].x), tanhf(f[3].y), tanhf(f[3].z), tanhf(f[3].w));
            *(float4*)&dst[(c0 + 1) * B_ + m8 + 4] = o;
        }
        if (kg == 1 && p > 0) {            // finalize h2(p)
            float4 f[4] = {{0,0,0,0},{0,0,0,0},{0,0,0,0},{0,0,0,0}};
            #pragma unroll
            for (int g = 0; g < 8; ++g) {
                int off = 4096 + (g * 32 + lane) * 16;
                #pragma unroll
                for (int j = 0; j < 4; ++j) {
                    float4 v = *(const float4*)&hst[off + j * 4];
                    f[j].x += v.x; f[j].y += v.y; f[j].z += v.z; f[j].w += v.w;
                }
            }
            f[0].x += b2c0; f[0].y += b2c0; f[0].z += b2c0; f[0].w += b2c0;
            f[1].x += b2c0; f[1].y += b2c0; f[1].z += b2c0; f[1].w += b2c0;
            f[2].x += b2c1; f[2].y += b2c1; f[2].z += b2c1; f[2].w += b2c1;
            f[3].x += b2c1; f[3].y += b2c1; f[3].z += b2c1; f[3].w += b2c1;
            float* dst = g_H2[pr];
            float4 o;
            o = make_float4(tanhf(f[0].x), tanhf(f[0].y), tanhf(f[0].z), tanhf(f[0].w));
            *(float4*)&dst[c0 * B_ + m8] = o;
            o = make_float4(tanhf(f[1].x), tanhf(f[1].y), tanhf(f[1].z), tanhf(f[1].w));
            *(float4*)&dst[c0 * B_ + m8 + 4] = o;
            o = make_float4(tanhf(f[2].x), tanhf(f[2].y), tanhf(f[2].z), tanhf(f[2].w));
            *(float4*)&dst[(c0 + 1) * B_ + m8] = o;
            o = make_float4(tanhf(f[3].x), tanhf(f[3].y), tanhf(f[3].z), tanhf(f[3].w));
            *(float4*)&dst[(c0 + 1) * B_ + m8 + 4] = o;
        }
        grid_barrier();
    }

    // epilogue: out[b] = sigmoid(h2(512) @ Wd + bd); h2(512) at parity 0
    if (c == 0 && tid < 128) {
        const int b = tid >> 1, h = tid & 1;
        const float* H2f = g_H2[0];
        float s = 0.f;
        #pragma unroll 8
        for (int k = h * 512; k < h * 512 + 512; ++k)
            s += __ldcg(&H2f[k * B_ + b]) * Wd[k];
        s += __shfl_xor_sync(0xffffffffu, s, 1);
        if (h == 0) out[b] = 1.f / (1.f + expf(-(s + bd[0])));
    }
}

// ================= launch =================
extern "C" void kernel_launch(void* const* d_in, const int* in_sizes, int n_in,
                              void* d_out, int out_size) {
    const int*   x   = (const int*)  d_in[0];
    const float* emb = (const float*)d_in[1];
    const float* Wi1 = (const float*)d_in[2];
    const float* Wh1 = (const float*)d_in[3];
    const float* b1  = (const float*)d_in[4];
    const float* Wi2 = (const float*)d_in[5];
    const float* Wh2 = (const float*)d_in[6];
    const float* b2  = (const float*)d_in[7];
    const float* Wd  = (const float*)d_in[8];
    const float* bd  = (const float*)d_in[9];
    float* out = (float*)d_out;

    cudaFuncSetAttribute(recur_kernel,
                         cudaFuncAttributeMaxDynamicSharedMemorySize, SMEM_BYTES);

    pre_kernel<<<dim3(16, 512), 256>>>(x, emb, Wi1, b1);
    recur_kernel<<<NCTA, TPB, SMEM_BYTES>>>(Wh1, Wi2, Wh2, b2, Wd, bd, out);
}

// round 6
// speedup vs baseline: 1.1123x; 1.1050x over previous
#include <cuda_runtime.h>
#include <math.h>

#define B_    64
#define S_    512
#define EMB_  512
#define HID_  1024
#define NCTA  128
#define NC    8          // output columns per CTA
#define TPB   256        // 8 warps; warp kg owns k-rows [kg*128, kg*128+128)

// SMEM floats: 3 duplicated weight arrays (3*16384) + reduction scratch (8192)
#define W_FLOATS   16384
#define RED_OFF    49152
#define SMEM_BYTES (57344 * 4)   // 229376 B

// -------- scratch (static device globals; no allocation) --------
__device__ float g_pre1[(size_t)S_ * HID_ * B_];   // [t][n][b]
__device__ float g_H1[2][HID_ * B_];               // [parity][k][m]
__device__ float g_H2[2][HID_ * B_];
__device__ unsigned g_cnt;
__device__ unsigned g_gen;

// -------- grid barrier (128 CTAs co-resident: 1 CTA/SM by smem) --------
// Spin uses ld.acquire.gpu + nanosleep back-off (no hot-poll livelock risk).
__device__ __forceinline__ unsigned ld_acq(const unsigned* p) {
    unsigned v;
    asm volatile("ld.acquire.gpu.u32 %0, [%1];" : "=r"(v) : "l"(p) : "memory");
    return v;
}
__device__ __forceinline__ void grid_barrier() {
    __syncthreads();
    if (threadIdx.x == 0) {
        __threadfence();                       // release prior STGs
        unsigned my = ld_acq(&g_gen);
        if (atomicAdd(&g_cnt, 1u) == NCTA - 1) {
            atomicExch(&g_cnt, 0u);
            asm volatile("st.release.gpu.u32 [%0], %1;" :: "l"(&g_gen), "r"(my + 1) : "memory");
        } else {
            while (ld_acq(&g_gen) == my) { __nanosleep(20); }
        }
    }
    __syncthreads();
}

// packed fp32x2 FMA: a.{lo,hi} += x.{lo,hi} * w.{lo,hi}
__device__ __forceinline__ void ffma2(unsigned long long& a,
                                      unsigned long long x,
                                      unsigned long long w) {
    asm("fma.rn.f32x2 %0, %1, %2, %0;" : "+l"(a) : "l"(x), "l"(w));
}

// 16B L2-direct load, bitcast to two packed-f32x2 operands
struct u64x2 { unsigned long long x, y; };
__device__ __forceinline__ u64x2 ldcg16(const float* p) {
    double2 v = __ldcg((const double2*)p);
    u64x2 r;
    r.x = (unsigned long long)__double_as_longlong(v.x);
    r.y = (unsigned long long)__double_as_longlong(v.y);
    return r;
}

// ================= precompute: pre1[t][n][b] = emb[x[b][t]] @ Wi1 + b1 =================
__global__ __launch_bounds__(256) void pre_kernel(
    const int* __restrict__ x, const float* __restrict__ emb,
    const float* __restrict__ Wi1, const float* __restrict__ b1)
{
    __shared__ int   tok[64];
    __shared__ float As[32 * 68];
    __shared__ float Bs[32 * 64];
    const int tid = threadIdx.x;
    const int t   = blockIdx.y;
    const int n0  = blockIdx.x * 64;

    if (tid < 64) tok[tid] = x[tid * S_ + t];
    __syncthreads();

    const int ty = tid >> 4, tx = tid & 15;
    float4 acc0 = {0,0,0,0}, acc1 = {0,0,0,0}, acc2 = {0,0,0,0}, acc3 = {0,0,0,0};

    const int b_l = tid >> 2, kq = tid & 3;
    for (int kt = 0; kt < 16; ++kt) {
        __syncthreads();
        #pragma unroll
        for (int j = 0; j < 2; ++j) {
            int k4 = kq * 4 + j * 16;
            float4 v = *(const float4*)&emb[(size_t)tok[b_l] * EMB_ + kt * 32 + k4];
            As[(k4+0)*68 + b_l] = v.x;
            As[(k4+1)*68 + b_l] = v.y;
            As[(k4+2)*68 + b_l] = v.z;
            As[(k4+3)*68 + b_l] = v.w;
        }
        #pragma unroll
        for (int j = 0; j < 2; ++j) {
            int kl = (tid >> 4) + j * 16;
            int nq = tid & 15;
            *(float4*)&Bs[kl*64 + nq*4] =
                *(const float4*)&Wi1[(size_t)(kt*32 + kl) * HID_ + n0 + nq*4];
        }
        __syncthreads();
        #pragma unroll
        for (int k = 0; k < 32; ++k) {
            float4 av = *(const float4*)&As[k*68 + ty*4];
            float4 bv = *(const float4*)&Bs[k*64 + tx*4];
            acc0.x += av.x*bv.x; acc0.y += av.x*bv.y; acc0.z += av.x*bv.z; acc0.w += av.x*bv.w;
            acc1.x += av.y*bv.x; acc1.y += av.y*bv.y; acc1.z += av.y*bv.z; acc1.w += av.y*bv.w;
            acc2.x += av.z*bv.x; acc2.y += av.z*bv.y; acc2.z += av.z*bv.z; acc2.w += av.z*bv.w;
            acc3.x += av.w*bv.x; acc3.y += av.w*bv.y; acc3.z += av.w*bv.z; acc3.w += av.w*bv.w;
        }
    }
    float4 b1v = *(const float4*)&b1[n0 + tx*4];
    acc0.x += b1v.x; acc0.y += b1v.y; acc0.z += b1v.z; acc0.w += b1v.w;
    acc1.x += b1v.x; acc1.y += b1v.y; acc1.z += b1v.z; acc1.w += b1v.w;
    acc2.x += b1v.x; acc2.y += b1v.y; acc2.z += b1v.z; acc2.w += b1v.w;
    acc3.x += b1v.x; acc3.y += b1v.y; acc3.z += b1v.z; acc3.w += b1v.w;

    float* outp = &g_pre1[(size_t)t * (HID_*B_)];
    float4 c;
    c = make_float4(acc0.x, acc1.x, acc2.x, acc3.x);
    *(float4*)&outp[(n0+tx*4+0)*B_ + ty*4] = c;
    c = make_float4(acc0.y, acc1.y, acc2.y, acc3.y);
    *(float4*)&outp[(n0+tx*4+1)*B_ + ty*4] = c;
    c = make_float4(acc0.z, acc1.z, acc2.z, acc3.z);
    *(float4*)&outp[(n0+tx*4+2)*B_ + ty*4] = c;
    c = make_float4(acc0.w, acc1.w, acc2.w, acc3.w);
    *(float4*)&outp[(n0+tx*4+3)*B_ + ty*4] = c;
}

// ================= persistent recurrent kernel =================
// Thread (kg=warp, cp, q): cols {c0,c0+1}, batch rows m8..m8+7, k-rows kg*128..+127.
// h is read straight from L2 (__ldcg) — no smem staging, no per-chunk syncs.
// Per phase: accumulate partials (f32x2), one syncthreads, 8-way smem reduction,
// kg0 finalizes h1 (adds pre1, tanh), kg1 finalizes h2. One grid barrier per phase.
__global__ void __launch_bounds__(TPB, 1) recur_kernel(
    const float* __restrict__ Wh1, const float* __restrict__ Wi2,
    const float* __restrict__ Wh2, const float* __restrict__ b2,
    const float* __restrict__ Wd,  const float* __restrict__ bd,
    float* __restrict__ out)
{
    extern __shared__ float sm[];
    float* Wh1d = sm;                    // [k][cp] float4 {wc0,wc0,wc1,wc1}
    float* Wi2d = sm + W_FLOATS;
    float* Wh2d = sm + 2 * W_FLOATS;
    float* red  = sm + RED_OFF;          // 8192 floats scratch

    const int tid  = threadIdx.x;
    const int c    = blockIdx.x;
    const int kg   = tid >> 5;           // warp = k-group 0..7
    const int lane = tid & 31;
    const int cp   = lane >> 3;          // col-pair 0..3
    const int q    = lane & 7;
    const int m8   = q * 8;
    const int c0   = c * NC + cp * 2;

    // fill duplicated weight slices
    for (int e = tid; e < HID_ * 4; e += TPB) {
        int k = e >> 2, p4 = e & 3;
        int col0 = c * NC + p4 * 2;
        float4 v;
        v.x = v.y = Wh1[(size_t)k * HID_ + col0];
        v.z = v.w = Wh1[(size_t)k * HID_ + col0 + 1];
        *(float4*)&Wh1d[e * 4] = v;
        v.x = v.y = Wi2[(size_t)k * HID_ + col0];
        v.z = v.w = Wi2[(size_t)k * HID_ + col0 + 1];
        *(float4*)&Wi2d[e * 4] = v;
        v.x = v.y = Wh2[(size_t)k * HID_ + col0];
        v.z = v.w = Wh2[(size_t)k * HID_ + col0 + 1];
        *(float4*)&Wh2d[e * 4] = v;
    }
    if (tid < 128) {
        float4 z = {0,0,0,0};
        *(float4*)&g_H1[0][c * NC * B_ + tid * 4] = z;
        *(float4*)&g_H2[0][c * NC * B_ + tid * 4] = z;
    }
    const float b2c0 = b2[c0], b2c1 = b2[c0 + 1];
    grid_barrier();

    for (int p = 0; p <= S_; ++p) {
        const int pr = p & 1;
        const float* H1r = g_H1[pr] + (kg << 7) * B_ + m8;    // h1(p), this warp's k-slice
        const float* H2r = g_H2[pr ^ 1] + (kg << 7) * B_ + m8;

        unsigned long long a1[2][4], a2[2][4];
        #pragma unroll
        for (int cc = 0; cc < 2; ++cc)
            #pragma unroll
            for (int j = 0; j < 4; ++j) { a1[cc][j] = 0ull; a2[cc][j] = 0ull; }

        const float4* wp1 = (const float4*)Wh1d + (kg << 7) * 4 + cp;
        const float4* wp2 = (const float4*)Wi2d + (kg << 7) * 4 + cp;
        const float4* wp3 = (const float4*)Wh2d + (kg << 7) * 4 + cp;

        #pragma unroll 4
        for (int kk = 0; kk < 128; ++kk) {
            u64x2 h1lo = ldcg16(H1r + kk * B_);
            u64x2 h1hi = ldcg16(H1r + kk * B_ + 4);
            u64x2 h2lo = ldcg16(H2r + kk * B_);
            u64x2 h2hi = ldcg16(H2r + kk * B_ + 4);
            ulonglong2 w1 = *(const ulonglong2*)&wp1[kk * 4];
            ulonglong2 wi = *(const ulonglong2*)&wp2[kk * 4];
            ulonglong2 w2 = *(const ulonglong2*)&wp3[kk * 4];
            #pragma unroll
            for (int cc = 0; cc < 2; ++cc) {
                unsigned long long w1c = cc ? w1.y : w1.x;
                unsigned long long wic = cc ? wi.y : wi.x;
                unsigned long long w2c = cc ? w2.y : w2.x;
                ffma2(a1[cc][0], h1lo.x, w1c);
                ffma2(a1[cc][1], h1lo.y, w1c);
                ffma2(a1[cc][2], h1hi.x, w1c);
                ffma2(a1[cc][3], h1hi.y, w1c);
                ffma2(a2[cc][0], h1lo.x, wic);
                ffma2(a2[cc][1], h1lo.y, wic);
                ffma2(a2[cc][2], h1hi.x, wic);
                ffma2(a2[cc][3], h1hi.y, wic);
                ffma2(a2[cc][0], h2lo.x, w2c);
                ffma2(a2[cc][1], h2lo.y, w2c);
                ffma2(a2[cc][2], h2hi.x, w2c);
                ffma2(a2[cc][3], h2hi.y, w2c);
            }
        }

        // write partials: A1 region floats [0,4096), A2 region [4096,8192)
        {
            int off = (kg * 32 + lane) * 16;
            ulonglong2 u;
            u.x = a1[0][0]; u.y = a1[0][1]; *(ulonglong2*)&red[off]      = u;
            u.x = a1[0][2]; u.y = a1[0][3]; *(ulonglong2*)&red[off + 4]  = u;
            u.x = a1[1][0]; u.y = a1[1][1]; *(ulonglong2*)&red[off + 8]  = u;
            u.x = a1[1][2]; u.y = a1[1][3]; *(ulonglong2*)&red[off + 12] = u;
            u.x = a2[0][0]; u.y = a2[0][1]; *(ulonglong2*)&red[4096 + off]      = u;
            u.x = a2[0][2]; u.y = a2[0][3]; *(ulonglong2*)&red[4096 + off + 4]  = u;
            u.x = a2[1][0]; u.y = a2[1][1]; *(ulonglong2*)&red[4096 + off + 8]  = u;
            u.x = a2[1][2]; u.y = a2[1][3]; *(ulonglong2*)&red[4096 + off + 12] = u;
        }
        __syncthreads();

        if (kg == 0 && p < S_) {           // finalize h1(p+1) = tanh(pre1 + sum)
            float4 f[4] = {{0,0,0,0},{0,0,0,0},{0,0,0,0},{0,0,0,0}};
            #pragma unroll
            for (int g = 0; g < 8; ++g) {
                int off = (g * 32 + lane) * 16;
                #pragma unroll
                for (int j = 0; j < 4; ++j) {
                    float4 v = *(const float4*)&red[off + j * 4];
                    f[j].x += v.x; f[j].y += v.y; f[j].z += v.z; f[j].w += v.w;
                }
            }
            const float* pp = &g_pre1[(size_t)p * (HID_ * B_)];
            float4 e0 = *(const float4*)&pp[c0 * B_ + m8];
            float4 e1 = *(const float4*)&pp[c0 * B_ + m8 + 4];
            float4 e2 = *(const float4*)&pp[(c0 + 1) * B_ + m8];
            float4 e3 = *(const float4*)&pp[(c0 + 1) * B_ + m8 + 4];
            f[0].x += e0.x; f[0].y += e0.y; f[0].z += e0.z; f[0].w += e0.w;
            f[1].x += e1.x; f[1].y += e1.y; f[1].z += e1.z; f[1].w += e1.w;
            f[2].x += e2.x; f[2].y += e2.y; f[2].z += e2.z; f[2].w += e2.w;
            f[3].x += e3.x; f[3].y += e3.y; f[3].z += e3.z; f[3].w += e3.w;
            float* dst = g_H1[pr ^ 1];
            float4 o;
            o = make_float4(tanhf(f[0].x), tanhf(f[0].y), tanhf(f[0].z), tanhf(f[0].w));
            *(float4*)&dst[c0 * B_ + m8] = o;
            o = make_float4(tanhf(f[1].x), tanhf(f[1].y), tanhf(f[1].z), tanhf(f[1].w));
            *(float4*)&dst[c0 * B_ + m8 + 4] = o;
            o = make_float4(tanhf(f[2].x), tanhf(f[2].y), tanhf(f[2].z), tanhf(f[2].w));
            *(float4*)&dst[(c0 + 1) * B_ + m8] = o;
            o = make_float4(tanhf(f[3].x), tanhf(f[3].y), tanhf(f[3].z), tanhf(f[3].w));
            *(float4*)&dst[(c0 + 1) * B_ + m8 + 4] = o;
        }
        if (kg == 1 && p > 0) {            // finalize h2(p)
            float4 f[4] = {{0,0,0,0},{0,0,0,0},{0,0,0,0},{0,0,0,0}};
            #pragma unroll
            for (int g = 0; g < 8; ++g) {
                int off = 4096 + (g * 32 + lane) * 16;
                #pragma unroll
                for (int j = 0; j < 4; ++j) {
                    float4 v = *(const float4*)&red[off + j * 4];
                    f[j].x += v.x; f[j].y += v.y; f[j].z += v.z; f[j].w += v.w;
                }
            }
            f[0].x += b2c0; f[0].y += b2c0; f[0].z += b2c0; f[0].w += b2c0;
            f[1].x += b2c0; f[1].y += b2c0; f[1].z += b2c0; f[1].w += b2c0;
            f[2].x += b2c1; f[2].y += b2c1; f[2].z += b2c1; f[2].w += b2c1;
            f[3].x += b2c1; f[3].y += b2c1; f[3].z += b2c1; f[3].w += b2c1;
            float* dst = g_H2[pr];
            float4 o;
            o = make_float4(tanhf(f[0].x), tanhf(f[0].y), tanhf(f[0].z), tanhf(f[0].w));
            *(float4*)&dst[c0 * B_ + m8] = o;
            o = make_float4(tanhf(f[1].x), tanhf(f[1].y), tanhf(f[1].z), tanhf(f[1].w));
            *(float4*)&dst[c0 * B_ + m8 + 4] = o;
            o = make_float4(tanhf(f[2].x), tanhf(f[2].y), tanhf(f[2].z), tanhf(f[2].w));
            *(float4*)&dst[(c0 + 1) * B_ + m8] = o;
            o = make_float4(tanhf(f[3].x), tanhf(f[3].y), tanhf(f[3].z), tanhf(f[3].w));
            *(float4*)&dst[(c0 + 1) * B_ + m8 + 4] = o;
        }
        grid_barrier();
    }

    // epilogue: out[b] = sigmoid(h2(512) @ Wd + bd); h2(512) at parity 0
    if (c == 0 && tid < 128) {
        const int b = tid >> 1, h = tid & 1;
        const float* H2f = g_H2[0];
        float s = 0.f;
        #pragma unroll 8
        for (int k = h * 512; k < h * 512 + 512; ++k)
            s += __ldcg(&H2f[k * B_ + b]) * Wd[k];
        s += __shfl_xor_sync(0xffffffffu, s, 1);
        if (h == 0) out[b] = 1.f / (1.f + expf(-(s + bd[0])));
    }
}

// ================= launch =================
extern "C" void kernel_launch(void* const* d_in, const int* in_sizes, int n_in,
                              void* d_out, int out_size) {
    const int*   x   = (const int*)  d_in[0];
    const float* emb = (const float*)d_in[1];
    const float* Wi1 = (const float*)d_in[2];
    const float* Wh1 = (const float*)d_in[3];
    const float* b1  = (const float*)d_in[4];
    const float* Wi2 = (const float*)d_in[5];
    const float* Wh2 = (const float*)d_in[6];
    const float* b2  = (const float*)d_in[7];
    const float* Wd  = (const float*)d_in[8];
    const float* bd  = (const float*)d_in[9];
    float* out = (float*)d_out;

    cudaFuncSetAttribute(recur_kernel,
                         cudaFuncAttributeMaxDynamicSharedMemorySize, SMEM_BYTES);

    pre_kernel<<<dim3(16, 512), 256>>>(x, emb, Wi1, b1);
    recur_kernel<<<NCTA, TPB, SMEM_BYTES>>>(Wh1, Wi2, Wh2, b2, Wd, bd, out);
}

// round 8
// speedup vs baseline: 1.9448x; 1.7485x over previous
#include <cuda_runtime.h>
#include <math.h>

#define B_    64
#define S_    512
#define EMB_  512
#define HID_  1024
#define NCTA  128
#define NC    8          // output columns per CTA
#define TPB   256        // 8 warps; warp kg owns k-rows [kg*128, kg*128+128)

// SMEM floats: 3 plain weight arrays (3*8192) + reduction scratch (8192) = 32768 floats
#define WSZ        8192          // floats per weight array [HID_][NC]
#define RED_OFF    24576
#define SMEM_BYTES (32768 * 4)   // 131072 B

// -------- scratch (static device globals; no allocation) --------
__device__ float g_pre1[(size_t)S_ * HID_ * B_];   // [t][n][b]
__device__ float g_H1[2][HID_ * B_];               // [parity][k][m]
__device__ float g_H2[2][HID_ * B_];
__device__ unsigned g_cnt;
__device__ unsigned g_gen;

// -------- grid barrier (PROVEN in round 6): atomic count + acquire/release gen ----
__device__ __forceinline__ unsigned ld_acq(const unsigned* p) {
    unsigned v;
    asm volatile("ld.acquire.gpu.u32 %0, [%1];" : "=r"(v) : "l"(p) : "memory");
    return v;
}
__device__ __forceinline__ void grid_barrier() {
    __syncthreads();
    if (threadIdx.x == 0) {
        __threadfence();                       // release prior STGs
        unsigned my = ld_acq(&g_gen);
        if (atomicAdd(&g_cnt, 1u) == NCTA - 1) {
            atomicExch(&g_cnt, 0u);
            asm volatile("st.release.gpu.u32 [%0], %1;" :: "l"(&g_gen), "r"(my + 1) : "memory");
        } else {
            while (ld_acq(&g_gen) == my) { __nanosleep(20); }
        }
    }
    __syncthreads();
}

// packed fp32x2 FMA: a.{lo,hi} += x.{lo,hi} * w.{lo,hi}
__device__ __forceinline__ void ffma2(unsigned long long& a,
                                      unsigned long long x,
                                      unsigned long long w) {
    asm("fma.rn.f32x2 %0, %1, %2, %0;" : "+l"(a) : "l"(x), "l"(w));
}
// duplicate one f32 into both halves of a packed f32x2 operand
__device__ __forceinline__ unsigned long long dup2(float w) {
    unsigned u = __float_as_uint(w);
    unsigned long long r;
    asm("mov.b64 %0, {%1, %1};" : "=l"(r) : "r"(u));
    return r;
}
// 16B L2-direct load, bitcast to two packed-f32x2 operands
struct u64x2 { unsigned long long x, y; };
__device__ __forceinline__ u64x2 ldcg16(const float* p) {
    double2 v = __ldcg((const double2*)p);
    u64x2 r;
    r.x = (unsigned long long)__double_as_longlong(v.x);
    r.y = (unsigned long long)__double_as_longlong(v.y);
    return r;
}

// ================= precompute: pre1[t][n][b] = emb[x[b][t]] @ Wi1 + b1 =================
__global__ __launch_bounds__(256) void pre_kernel(
    const int* __restrict__ x, const float* __restrict__ emb,
    const float* __restrict__ Wi1, const float* __restrict__ b1)
{
    __shared__ int   tok[64];
    __shared__ float As[32 * 68];
    __shared__ float Bs[32 * 64];
    const int tid = threadIdx.x;
    const int t   = blockIdx.y;
    const int n0  = blockIdx.x * 64;

    if (tid < 64) tok[tid] = x[tid * S_ + t];
    __syncthreads();

    const int ty = tid >> 4, tx = tid & 15;
    float4 acc0 = {0,0,0,0}, acc1 = {0,0,0,0}, acc2 = {0,0,0,0}, acc3 = {0,0,0,0};

    const int b_l = tid >> 2, kq = tid & 3;
    for (int kt = 0; kt < 16; ++kt) {
        __syncthreads();
        #pragma unroll
        for (int j = 0; j < 2; ++j) {
            int k4 = kq * 4 + j * 16;
            float4 v = *(const float4*)&emb[(size_t)tok[b_l] * EMB_ + kt * 32 + k4];
            As[(k4+0)*68 + b_l] = v.x;
            As[(k4+1)*68 + b_l] = v.y;
            As[(k4+2)*68 + b_l] = v.z;
            As[(k4+3)*68 + b_l] = v.w;
        }
        #pragma unroll
        for (int j = 0; j < 2; ++j) {
            int kl = (tid >> 4) + j * 16;
            int nq = tid & 15;
            *(float4*)&Bs[kl*64 + nq*4] =
                *(const float4*)&Wi1[(size_t)(kt*32 + kl) * HID_ + n0 + nq*4];
        }
        __syncthreads();
        #pragma unroll
        for (int k = 0; k < 32; ++k) {
            float4 av = *(const float4*)&As[k*68 + ty*4];
            float4 bv = *(const float4*)&Bs[k*64 + tx*4];
            acc0.x += av.x*bv.x; acc0.y += av.x*bv.y; acc0.z += av.x*bv.z; acc0.w += av.x*bv.w;
            acc1.x += av.y*bv.x; acc1.y += av.y*bv.y; acc1.z += av.y*bv.z; acc1.w += av.y*bv.w;
            acc2.x += av.z*bv.x; acc2.y += av.z*bv.y; acc2.z += av.z*bv.z; acc2.w += av.z*bv.w;
            acc3.x += av.w*bv.x; acc3.y += av.w*bv.y; acc3.z += av.w*bv.z; acc3.w += av.w*bv.w;
        }
    }
    float4 b1v = *(const float4*)&b1[n0 + tx*4];
    acc0.x += b1v.x; acc0.y += b1v.y; acc0.z += b1v.z; acc0.w += b1v.w;
    acc1.x += b1v.x; acc1.y += b1v.y; acc1.z += b1v.z; acc1.w += b1v.w;
    acc2.x += b1v.x; acc2.y += b1v.y; acc2.z += b1v.z; acc2.w += b1v.w;
    acc3.x += b1v.x; acc3.y += b1v.y; acc3.z += b1v.z; acc3.w += b1v.w;

    float* outp = &g_pre1[(size_t)t * (HID_*B_)];
    float4 c;
    c = make_float4(acc0.x, acc1.x, acc2.x, acc3.x);
    *(float4*)&outp[(n0+tx*4+0)*B_ + ty*4] = c;
    c = make_float4(acc0.y, acc1.y, acc2.y, acc3.y);
    *(float4*)&outp[(n0+tx*4+1)*B_ + ty*4] = c;
    c = make_float4(acc0.z, acc1.z, acc2.z, acc3.z);
    *(float4*)&outp[(n0+tx*4+2)*B_ + ty*4] = c;
    c = make_float4(acc0.w, acc1.w, acc2.w, acc3.w);
    *(float4*)&outp[(n0+tx*4+3)*B_ + ty*4] = c;
}

// ================= persistent recurrent kernel =================
// Lane (cp,q): cp in {0,1} col-quad, q in {0..15} m-quad. Thread covers cols
// c0..c0+3 and batch rows m4..m4+3; warp kg covers k-rows kg*128..+127.
// h read straight from L2 (ldcg), 2x column-group redundancy (was 4x in R6).
// Weights plain [k][8] in smem; {w,w} pairs built in ALU (dup2).
__global__ void __launch_bounds__(TPB, 1) recur_kernel(
    const float* __restrict__ Wh1, const float* __restrict__ Wi2,
    const float* __restrict__ Wh2, const float* __restrict__ b2,
    const float* __restrict__ Wd,  const float* __restrict__ bd,
    float* __restrict__ out)
{
    extern __shared__ float sm[];
    float* Ws1 = sm;                 // [HID_][8]
    float* Wsi = sm + WSZ;
    float* Ws2 = sm + 2 * WSZ;
    float* red = sm + RED_OFF;       // 8192 floats scratch

    const int tid  = threadIdx.x;
    const int c    = blockIdx.x;
    const int kg   = tid >> 5;           // warp = k-group 0..7
    const int lane = tid & 31;
    const int cp   = lane >> 4;          // col-quad 0..1
    const int q    = lane & 15;          // m-quad 0..15
    const int m4   = q * 4;
    const int c0   = c * NC + cp * 4;

    // fill plain weight slices [k][8]
    for (int e = tid; e < HID_ * 2; e += TPB) {
        int k = e >> 1, h4 = (e & 1) * 4;
        int col = c * NC + h4;
        float4 v;
        v.x = Wh1[(size_t)k * HID_ + col];     v.y = Wh1[(size_t)k * HID_ + col + 1];
        v.z = Wh1[(size_t)k * HID_ + col + 2]; v.w = Wh1[(size_t)k * HID_ + col + 3];
        *(float4*)&Ws1[k * 8 + h4] = v;
        v.x = Wi2[(size_t)k * HID_ + col];     v.y = Wi2[(size_t)k * HID_ + col + 1];
        v.z = Wi2[(size_t)k * HID_ + col + 2]; v.w = Wi2[(size_t)k * HID_ + col + 3];
        *(float4*)&Wsi[k * 8 + h4] = v;
        v.x = Wh2[(size_t)k * HID_ + col];     v.y = Wh2[(size_t)k * HID_ + col + 1];
        v.z = Wh2[(size_t)k * HID_ + col + 2]; v.w = Wh2[(size_t)k * HID_ + col + 3];
        *(float4*)&Ws2[k * 8 + h4] = v;
    }
    if (tid < 128) {
        float4 z = {0,0,0,0};
        *(float4*)&g_H1[0][c * NC * B_ + tid * 4] = z;
        *(float4*)&g_H2[0][c * NC * B_ + tid * 4] = z;
    }
    const float4 b2v = *(const float4*)&b2[c0];
    grid_barrier();

    for (int p = 0; p <= S_; ++p) {
        const int pr = p & 1;
        const float* H1r = g_H1[pr] + (kg << 7) * B_ + m4;    // h1(p), warp k-slice
        const float* H2r = g_H2[pr ^ 1] + (kg << 7) * B_ + m4;

        unsigned long long a1[4][2], a2[4][2];
        #pragma unroll
        for (int ci = 0; ci < 4; ++ci) {
            a1[ci][0] = a1[ci][1] = 0ull;
            a2[ci][0] = a2[ci][1] = 0ull;
        }
        if (kg == 0 && p < S_) {         // seed a1 with pre1 (this thread's tile)
            const float* pp = &g_pre1[(size_t)p * (HID_ * B_)];
            #pragma unroll
            for (int ci = 0; ci < 4; ++ci) {
                ulonglong2 v = *(const ulonglong2*)&pp[(c0 + ci) * B_ + m4];
                a1[ci][0] = v.x; a1[ci][1] = v.y;
            }
        }

        const float* w1p = Ws1 + (kg << 7) * 8 + cp * 4;
        const float* wip = Wsi + (kg << 7) * 8 + cp * 4;
        const float* w2p = Ws2 + (kg << 7) * 8 + cp * 4;

        #pragma unroll 8
        for (int kk = 0; kk < 128; ++kk) {
            u64x2 h1 = ldcg16(H1r + kk * B_);
            u64x2 h2 = ldcg16(H2r + kk * B_);
            float4 w1 = *(const float4*)&w1p[kk * 8];
            float4 wi = *(const float4*)&wip[kk * 8];
            float4 w2 = *(const float4*)&w2p[kk * 8];
            const float w1a[4] = {w1.x, w1.y, w1.z, w1.w};
            const float wia[4] = {wi.x, wi.y, wi.z, wi.w};
            const float w2a[4] = {w2.x, w2.y, w2.z, w2.w};
            #pragma unroll
            for (int ci = 0; ci < 4; ++ci) {
                unsigned long long w1d = dup2(w1a[ci]);
                unsigned long long wid = dup2(wia[ci]);
                unsigned long long w2d = dup2(w2a[ci]);
                ffma2(a1[ci][0], h1.x, w1d);
                ffma2(a1[ci][1], h1.y, w1d);
                ffma2(a2[ci][0], h1.x, wid);
                ffma2(a2[ci][1], h1.y, wid);
                ffma2(a2[ci][0], h2.x, w2d);
                ffma2(a2[ci][1], h2.y, w2d);
            }
        }

        // partials -> smem: A1 floats [0,4096), A2 [4096,8192)
        {
            int off = (kg * 32 + lane) * 16;
            ulonglong2 u;
            u.x = a1[0][0]; u.y = a1[0][1]; *(ulonglong2*)&red[off]      = u;
            u.x = a1[1][0]; u.y = a1[1][1]; *(ulonglong2*)&red[off + 4]  = u;
            u.x = a1[2][0]; u.y = a1[2][1]; *(ulonglong2*)&red[off + 8]  = u;
            u.x = a1[3][0]; u.y = a1[3][1]; *(ulonglong2*)&red[off + 12] = u;
            u.x = a2[0][0]; u.y = a2[0][1]; *(ulonglong2*)&red[4096 + off]      = u;
            u.x = a2[1][0]; u.y = a2[1][1]; *(ulonglong2*)&red[4096 + off + 4]  = u;
            u.x = a2[2][0]; u.y = a2[2][1]; *(ulonglong2*)&red[4096 + off + 8]  = u;
            u.x = a2[3][0]; u.y = a2[3][1]; *(ulonglong2*)&red[4096 + off + 12] = u;
        }
        __syncthreads();

        if (kg == 0 && p < S_) {           // finalize h1(p+1) = tanh(sum) (pre seeded)
            float4 f[4] = {{0,0,0,0},{0,0,0,0},{0,0,0,0},{0,0,0,0}};
            #pragma unroll
            for (int g = 0; g < 8; ++g) {
                int off = (g * 32 + lane) * 16;
                #pragma unroll
                for (int j = 0; j < 4; ++j) {
                    float4 v = *(const float4*)&red[off + j * 4];
                    f[j].x += v.x; f[j].y += v.y; f[j].z += v.z; f[j].w += v.w;
                }
            }
            float* dst = g_H1[pr ^ 1];
            #pragma unroll
            for (int j = 0; j < 4; ++j) {
                float4 o = make_float4(tanhf(f[j].x), tanhf(f[j].y),
                                       tanhf(f[j].z), tanhf(f[j].w));
                *(float4*)&dst[(c0 + j) * B_ + m4] = o;
            }
        }
        if (kg == 1 && p > 0) {            // finalize h2(p)
            float4 f[4] = {{0,0,0,0},{0,0,0,0},{0,0,0,0},{0,0,0,0}};
            #pragma unroll
            for (int g = 0; g < 8; ++g) {
                int off = 4096 + (g * 32 + lane) * 16;
                #pragma unroll
                for (int j = 0; j < 4; ++j) {
                    float4 v = *(const float4*)&red[off + j * 4];
                    f[j].x += v.x; f[j].y += v.y; f[j].z += v.z; f[j].w += v.w;
                }
            }
            const float bb[4] = {b2v.x, b2v.y, b2v.z, b2v.w};
            float* dst = g_H2[pr];
            #pragma unroll
            for (int j = 0; j < 4; ++j) {
                float4 o = make_float4(tanhf(f[j].x + bb[j]), tanhf(f[j].y + bb[j]),
                                       tanhf(f[j].z + bb[j]), tanhf(f[j].w + bb[j]));
                *(float4*)&dst[(c0 + j) * B_ + m4] = o;
            }
        }
        grid_barrier();
    }

    // epilogue: out[b] = sigmoid(h2(512) @ Wd + bd); h2(512) at parity 0
    if (c == 0 && tid < 128) {
        const int b = tid >> 1, h = tid & 1;
        const float* H2f = g_H2[0];
        float s = 0.f;
        #pragma unroll 8
        for (int k = h * 512; k < h * 512 + 512; ++k)
            s += __ldcg(&H2f[k * B_ + b]) * Wd[k];
        s += __shfl_xor_sync(0xffffffffu, s, 1);
        if (h == 0) out[b] = 1.f / (1.f + expf(-(s + bd[0])));
    }
}

// ================= launch =================
extern "C" void kernel_launch(void* const* d_in, const int* in_sizes, int n_in,
                              void* d_out, int out_size) {
    const int*   x   = (const int*)  d_in[0];
    const float* emb = (const float*)d_in[1];
    const float* Wi1 = (const float*)d_in[2];
    const float* Wh1 = (const float*)d_in[3];
    const float* b1  = (const float*)d_in[4];
    const float* Wi2 = (const float*)d_in[5];
    const float* Wh2 = (const float*)d_in[6];
    const float* b2  = (const float*)d_in[7];
    const float* Wd  = (const float*)d_in[8];
    const float* bd  = (const float*)d_in[9];
    float* out = (float*)d_out;

    cudaFuncSetAttribute(recur_kernel,
                         cudaFuncAttributeMaxDynamicSharedMemorySize, SMEM_BYTES);

    pre_kernel<<<dim3(16, 512), 256>>>(x, emb, Wi1, b1);
    recur_kernel<<<NCTA, TPB, SMEM_BYTES>>>(Wh1, Wi2, Wh2, b2, Wd, bd, out);
}

// round 9
// speedup vs baseline: 2.0131x; 1.0351x over previous
#include <cuda_runtime.h>
#include <math.h>

#define B_    64
#define S_    512
#define EMB_  512
#define HID_  1024
#define NCTA  128
#define NC    8          // output columns per CTA
#define TPB   512        // 16 warps; warp kg owns k-rows [kg*64, kg*64+64)
#define NW    16

// SMEM floats: 3 plain weight arrays (3*8192) + reduction scratch (16384) = 40960 floats
#define WSZ        8192          // floats per weight array [HID_][NC]
#define RED_OFF    24576
#define SMEM_BYTES (40960 * 4)   // 163840 B -> 1 CTA/SM

// -------- scratch (static device globals; no allocation) --------
__device__ float g_pre1[(size_t)S_ * HID_ * B_];   // [t][n][b]
__device__ float g_H1[2][HID_ * B_];               // [parity][k][m]
__device__ float g_H2[2][HID_ * B_];
__device__ unsigned g_cnt;
__device__ unsigned g_gen;

// -------- grid barrier (proven R6/R8): atomic count + acquire/release gen ----
__device__ __forceinline__ unsigned ld_acq(const unsigned* p) {
    unsigned v;
    asm volatile("ld.acquire.gpu.u32 %0, [%1];" : "=r"(v) : "l"(p) : "memory");
    return v;
}
__device__ __forceinline__ void grid_barrier() {
    __syncthreads();
    if (threadIdx.x == 0) {
        __threadfence();
        unsigned my = ld_acq(&g_gen);
        if (atomicAdd(&g_cnt, 1u) == NCTA - 1) {
            atomicExch(&g_cnt, 0u);
            asm volatile("st.release.gpu.u32 [%0], %1;" :: "l"(&g_gen), "r"(my + 1) : "memory");
        } else {
            while (ld_acq(&g_gen) == my) { __nanosleep(20); }
        }
    }
    __syncthreads();
}

// packed fp32x2 FMA
__device__ __forceinline__ void ffma2(unsigned long long& a,
                                      unsigned long long x,
                                      unsigned long long w) {
    asm("fma.rn.f32x2 %0, %1, %2, %0;" : "+l"(a) : "l"(x), "l"(w));
}
__device__ __forceinline__ unsigned long long dup2(float w) {
    unsigned u = __float_as_uint(w);
    unsigned long long r;
    asm("mov.b64 %0, {%1, %1};" : "=l"(r) : "r"(u));
    return r;
}
struct u64x2 { unsigned long long x, y; };
__device__ __forceinline__ u64x2 ldcg16(const float* p) {
    double2 v = __ldcg((const double2*)p);
    u64x2 r;
    r.x = (unsigned long long)__double_as_longlong(v.x);
    r.y = (unsigned long long)__double_as_longlong(v.y);
    return r;
}

// ================= precompute: pre1[t][n][b] = emb[x[b][t]] @ Wi1 + b1 =================
__global__ __launch_bounds__(256) void pre_kernel(
    const int* __restrict__ x, const float* __restrict__ emb,
    const float* __restrict__ Wi1, const float* __restrict__ b1)
{
    __shared__ int   tok[64];
    __shared__ float As[32 * 68];
    __shared__ float Bs[32 * 64];
    const int tid = threadIdx.x;
    const int t   = blockIdx.y;
    const int n0  = blockIdx.x * 64;

    if (tid < 64) tok[tid] = x[tid * S_ + t];
    __syncthreads();

    const int ty = tid >> 4, tx = tid & 15;
    float4 acc0 = {0,0,0,0}, acc1 = {0,0,0,0}, acc2 = {0,0,0,0}, acc3 = {0,0,0,0};

    const int b_l = tid >> 2, kq = tid & 3;
    for (int kt = 0; kt < 16; ++kt) {
        __syncthreads();
        #pragma unroll
        for (int j = 0; j < 2; ++j) {
            int k4 = kq * 4 + j * 16;
            float4 v = *(const float4*)&emb[(size_t)tok[b_l] * EMB_ + kt * 32 + k4];
            As[(k4+0)*68 + b_l] = v.x;
            As[(k4+1)*68 + b_l] = v.y;
            As[(k4+2)*68 + b_l] = v.z;
            As[(k4+3)*68 + b_l] = v.w;
        }
        #pragma unroll
        for (int j = 0; j < 2; ++j) {
            int kl = (tid >> 4) + j * 16;
            int nq = tid & 15;
            *(float4*)&Bs[kl*64 + nq*4] =
                *(const float4*)&Wi1[(size_t)(kt*32 + kl) * HID_ + n0 + nq*4];
        }
        __syncthreads();
        #pragma unroll
        for (int k = 0; k < 32; ++k) {
            float4 av = *(const float4*)&As[k*68 + ty*4];
            float4 bv = *(const float4*)&Bs[k*64 + tx*4];
            acc0.x += av.x*bv.x; acc0.y += av.x*bv.y; acc0.z += av.x*bv.z; acc0.w += av.x*bv.w;
            acc1.x += av.y*bv.x; acc1.y += av.y*bv.y; acc1.z += av.y*bv.z; acc1.w += av.y*bv.w;
            acc2.x += av.z*bv.x; acc2.y += av.z*bv.y; acc2.z += av.z*bv.z; acc2.w += av.z*bv.w;
            acc3.x += av.w*bv.x; acc3.y += av.w*bv.y; acc3.z += av.w*bv.z; acc3.w += av.w*bv.w;
        }
    }
    float4 b1v = *(const float4*)&b1[n0 + tx*4];
    acc0.x += b1v.x; acc0.y += b1v.y; acc0.z += b1v.z; acc0.w += b1v.w;
    acc1.x += b1v.x; acc1.y += b1v.y; acc1.z += b1v.z; acc1.w += b1v.w;
    acc2.x += b1v.x; acc2.y += b1v.y; acc2.z += b1v.z; acc2.w += b1v.w;
    acc3.x += b1v.x; acc3.y += b1v.y; acc3.z += b1v.z; acc3.w += b1v.w;

    float* outp = &g_pre1[(size_t)t * (HID_*B_)];
    float4 c;
    c = make_float4(acc0.x, acc1.x, acc2.x, acc3.x);
    *(float4*)&outp[(n0+tx*4+0)*B_ + ty*4] = c;
    c = make_float4(acc0.y, acc1.y, acc2.y, acc3.y);
    *(float4*)&outp[(n0+tx*4+1)*B_ + ty*4] = c;
    c = make_float4(acc0.z, acc1.z, acc2.z, acc3.z);
    *(float4*)&outp[(n0+tx*4+2)*B_ + ty*4] = c;
    c = make_float4(acc0.w, acc1.w, acc2.w, acc3.w);
    *(float4*)&outp[(n0+tx*4+3)*B_ + ty*4] = c;
}

// ================= persistent recurrent kernel =================
// 16 warps. Warp kg owns k-rows [kg*64, kg*64+64). Lane (cp,q): cols c0..c0+3,
// batch rows m4..m4+3. h read from L2 (ldcg); weights plain [k][8] in smem,
// {w,w} pairs built via dup2 (ALU). 16-way smem reduction per phase.
__global__ void __launch_bounds__(TPB, 1) recur_kernel(
    const float* __restrict__ Wh1, const float* __restrict__ Wi2,
    const float* __restrict__ Wh2, const float* __restrict__ b2,
    const float* __restrict__ Wd,  const float* __restrict__ bd,
    float* __restrict__ out)
{
    extern __shared__ float sm[];
    float* Ws1 = sm;                 // [HID_][8]
    float* Wsi = sm + WSZ;
    float* Ws2 = sm + 2 * WSZ;
    float* red = sm + RED_OFF;       // 16384 floats scratch

    const int tid  = threadIdx.x;
    const int c    = blockIdx.x;
    const int kg   = tid >> 5;           // warp = k-group 0..15
    const int lane = tid & 31;
    const int cp   = lane >> 4;          // col-quad 0..1
    const int q    = lane & 15;          // m-quad 0..15
    const int m4   = q * 4;
    const int c0   = c * NC + cp * 4;

    // fill plain weight slices [k][8]
    for (int e = tid; e < HID_ * 2; e += TPB) {
        int k = e >> 1, h4 = (e & 1) * 4;
        int col = c * NC + h4;
        float4 v;
        v.x = Wh1[(size_t)k * HID_ + col];     v.y = Wh1[(size_t)k * HID_ + col + 1];
        v.z = Wh1[(size_t)k * HID_ + col + 2]; v.w = Wh1[(size_t)k * HID_ + col + 3];
        *(float4*)&Ws1[k * 8 + h4] = v;
        v.x = Wi2[(size_t)k * HID_ + col];     v.y = Wi2[(size_t)k * HID_ + col + 1];
        v.z = Wi2[(size_t)k * HID_ + col + 2]; v.w = Wi2[(size_t)k * HID_ + col + 3];
        *(float4*)&Wsi[k * 8 + h4] = v;
        v.x = Wh2[(size_t)k * HID_ + col];     v.y = Wh2[(size_t)k * HID_ + col + 1];
        v.z = Wh2[(size_t)k * HID_ + col + 2]; v.w = Wh2[(size_t)k * HID_ + col + 3];
        *(float4*)&Ws2[k * 8 + h4] = v;
    }
    if (tid < 128) {
        float4 z = {0,0,0,0};
        *(float4*)&g_H1[0][c * NC * B_ + tid * 4] = z;
        *(float4*)&g_H2[0][c * NC * B_ + tid * 4] = z;
    }
    const float4 b2v = *(const float4*)&b2[c0];
    grid_barrier();

    for (int p = 0; p <= S_; ++p) {
        const int pr = p & 1;
        const float* H1r = g_H1[pr] + (kg << 6) * B_ + m4;    // h1(p), warp k-slice
        const float* H2r = g_H2[pr ^ 1] + (kg << 6) * B_ + m4;

        unsigned long long a1[4][2], a2[4][2];
        #pragma unroll
        for (int ci = 0; ci < 4; ++ci) {
            a1[ci][0] = a1[ci][1] = 0ull;
            a2[ci][0] = a2[ci][1] = 0ull;
        }
        if (kg == 0 && p < S_) {         // seed a1 with pre1 (this thread's tile)
            const float* pp = &g_pre1[(size_t)p * (HID_ * B_)];
            #pragma unroll
            for (int ci = 0; ci < 4; ++ci) {
                ulonglong2 v = *(const ulonglong2*)&pp[(c0 + ci) * B_ + m4];
                a1[ci][0] = v.x; a1[ci][1] = v.y;
            }
        }

        const float* w1p = Ws1 + (kg << 6) * 8 + cp * 4;
        const float* wip = Wsi + (kg << 6) * 8 + cp * 4;
        const float* w2p = Ws2 + (kg << 6) * 8 + cp * 4;

        #pragma unroll 8
        for (int kk = 0; kk < 64; ++kk) {
            u64x2 h1 = ldcg16(H1r + kk * B_);
            u64x2 h2 = ldcg16(H2r + kk * B_);
            float4 w1 = *(const float4*)&w1p[kk * 8];
            float4 wi = *(const float4*)&wip[kk * 8];
            float4 w2 = *(const float4*)&w2p[kk * 8];
            const float w1a[4] = {w1.x, w1.y, w1.z, w1.w};
            const float wia[4] = {wi.x, wi.y, wi.z, wi.w};
            const float w2a[4] = {w2.x, w2.y, w2.z, w2.w};
            #pragma unroll
            for (int ci = 0; ci < 4; ++ci) {
                unsigned long long w1d = dup2(w1a[ci]);
                unsigned long long wid = dup2(wia[ci]);
                unsigned long long w2d = dup2(w2a[ci]);
                ffma2(a1[ci][0], h1.x, w1d);
                ffma2(a1[ci][1], h1.y, w1d);
                ffma2(a2[ci][0], h1.x, wid);
                ffma2(a2[ci][1], h1.y, wid);
                ffma2(a2[ci][0], h2.x, w2d);
                ffma2(a2[ci][1], h2.y, w2d);
            }
        }

        // partials -> smem: A1 floats [0,8192), A2 [8192,16384)
        {
            int off = (kg * 32 + lane) * 16;
            ulonglong2 u;
            u.x = a1[0][0]; u.y = a1[0][1]; *(ulonglong2*)&red[off]      = u;
            u.x = a1[1][0]; u.y = a1[1][1]; *(ulonglong2*)&red[off + 4]  = u;
            u.x = a1[2][0]; u.y = a1[2][1]; *(ulonglong2*)&red[off + 8]  = u;
            u.x = a1[3][0]; u.y = a1[3][1]; *(ulonglong2*)&red[off + 12] = u;
            u.x = a2[0][0]; u.y = a2[0][1]; *(ulonglong2*)&red[8192 + off]      = u;
            u.x = a2[1][0]; u.y = a2[1][1]; *(ulonglong2*)&red[8192 + off + 4]  = u;
            u.x = a2[2][0]; u.y = a2[2][1]; *(ulonglong2*)&red[8192 + off + 8]  = u;
            u.x = a2[3][0]; u.y = a2[3][1]; *(ulonglong2*)&red[8192 + off + 12] = u;
        }
        __syncthreads();

        if (kg == 0 && p < S_) {           // finalize h1(p+1) = tanh(sum) (pre seeded)
            float4 f[4] = {{0,0,0,0},{0,0,0,0},{0,0,0,0},{0,0,0,0}};
            #pragma unroll
            for (int g = 0; g < NW; ++g) {
                int off = (g * 32 + lane) * 16;
                #pragma unroll
                for (int j = 0; j < 4; ++j) {
                    float4 v = *(const float4*)&red[off + j * 4];
                    f[j].x += v.x; f[j].y += v.y; f[j].z += v.z; f[j].w += v.w;
                }
            }
            float* dst = g_H1[pr ^ 1];
            #pragma unroll
            for (int j = 0; j < 4; ++j) {
                float4 o = make_float4(tanhf(f[j].x), tanhf(f[j].y),
                                       tanhf(f[j].z), tanhf(f[j].w));
                *(float4*)&dst[(c0 + j) * B_ + m4] = o;
            }
        }
        if (kg == 1 && p > 0) {            // finalize h2(p)
            float4 f[4] = {{0,0,0,0},{0,0,0,0},{0,0,0,0},{0,0,0,0}};
            #pragma unroll
            for (int g = 0; g < NW; ++g) {
                int off = 8192 + (g * 32 + lane) * 16;
                #pragma unroll
                for (int j = 0; j < 4; ++j) {
                    float4 v = *(const float4*)&red[off + j * 4];
                    f[j].x += v.x; f[j].y += v.y; f[j].z += v.z; f[j].w += v.w;
                }
            }
            const float bb[4] = {b2v.x, b2v.y, b2v.z, b2v.w};
            float* dst = g_H2[pr];
            #pragma unroll
            for (int j = 0; j < 4; ++j) {
                float4 o = make_float4(tanhf(f[j].x + bb[j]), tanhf(f[j].y + bb[j]),
                                       tanhf(f[j].z + bb[j]), tanhf(f[j].w + bb[j]));
                *(float4*)&dst[(c0 + j) * B_ + m4] = o;
            }
        }
        grid_barrier();
    }

    // epilogue: out[b] = sigmoid(h2(512) @ Wd + bd); h2(512) at parity 0
    if (c == 0 && tid < 128) {
        const int b = tid >> 1, h = tid & 1;
        const float* H2f = g_H2[0];
        float s = 0.f;
        #pragma unroll 8
        for (int k = h * 512; k < h * 512 + 512; ++k)
            s += __ldcg(&H2f[k * B_ + b]) * Wd[k];
        s += __shfl_xor_sync(0xffffffffu, s, 1);
        if (h == 0) out[b] = 1.f / (1.f + expf(-(s + bd[0])));
    }
}

// ================= launch =================
extern "C" void kernel_launch(void* const* d_in, const int* in_sizes, int n_in,
                              void* d_out, int out_size) {
    const int*   x   = (const int*)  d_in[0];
    const float* emb = (const float*)d_in[1];
    const float* Wi1 = (const float*)d_in[2];
    const float* Wh1 = (const float*)d_in[3];
    const float* b1  = (const float*)d_in[4];
    const float* Wi2 = (const float*)d_in[5];
    const float* Wh2 = (const float*)d_in[6];
    const float* b2  = (const float*)d_in[7];
    const float* Wd  = (const float*)d_in[8];
    const float* bd  = (const float*)d_in[9];
    float* out = (float*)d_out;

    cudaFuncSetAttribute(recur_kernel,
                         cudaFuncAttributeMaxDynamicSharedMemorySize, SMEM_BYTES);

    pre_kernel<<<dim3(16, 512), 256>>>(x, emb, Wi1, b1);
    recur_kernel<<<NCTA, TPB, SMEM_BYTES>>>(Wh1, Wi2, Wh2, b2, Wd, bd, out);
}